// round 11
// baseline (speedup 1.0000x reference)
#include <cuda_runtime.h>
#include <cuda_bf16.h>
#include <math.h>

#define T_TOK 8192
#define DIMD  4096
#define NE    8
#define HH    1024
#define SHH   2048

#define BM 128
#define BN 64
#define BK 16
#define NTHR 256

#define AS_LD 130
#define BS_LD 68

// ------------------------------ device scratch ------------------------------
__device__ int   g_counts[NE];
__device__ int   g_offsets[NE + 1];
__device__ int   g_pos[NE];
__device__ int   g_top_idx[T_TOK * 2];
__device__ float g_top_w[T_TOK * 2];
__device__ int   g_tok[T_TOK * 2];
__device__ float g_tokw[T_TOK * 2];
__device__ float g_bufA[(size_t)T_TOK * 2 * HH];   // 64 MB
__device__ float g_bufB[(size_t)T_TOK * 2 * HH];   // 64 MB

typedef unsigned long long u64;

// ------------------------------ f32x2 helpers -------------------------------
__device__ __forceinline__ u64 ffma2(u64 a, u64 b, u64 c) {
    u64 d;
    asm("fma.rn.f32x2 %0, %1, %2, %3;" : "=l"(d) : "l"(a), "l"(b), "l"(c));
    return d;
}
__device__ __forceinline__ u64 pack2(float x, float y) {
    u64 d;
    asm("mov.b64 %0, {%1, %2};" : "=l"(d) : "f"(x), "f"(y));
    return d;
}
__device__ __forceinline__ float2 unpack2(u64 v) {
    float2 r;
    asm("mov.b64 {%0, %1}, %2;" : "=f"(r.x), "=f"(r.y) : "l"(v));
    return r;
}
__device__ __forceinline__ float siluf(float x) { return x / (1.0f + expf(-x)); }

// ------------------------------ epilogue helper -----------------------------
// EPI 0: C[row, c0..c0+3] = v                 (plain store)
// EPI 1: C[row, c] = silu(other[row, c]) * v  (SwiGLU fuse)
// EPI 2: out[tok[row], c] += tw[row] * v      (scatter-combine)
template <int EPI>
__device__ __forceinline__ void epi_row(
    int row, int M, int c0,
    float va, float vb, float vc, float vd,
    float* __restrict__ C, int ldc,
    const float* __restrict__ other,
    const int* __restrict__ tok, const float* __restrict__ tw,
    float* __restrict__ outp, int out_ld)
{
    if (row >= M) return;
    if (EPI == 0) {
        *reinterpret_cast<float4*>(&C[(size_t)row * ldc + c0]) =
            make_float4(va, vb, vc, vd);
    } else if (EPI == 1) {
        float4 g4 = *reinterpret_cast<const float4*>(&other[(size_t)row * ldc + c0]);
        *reinterpret_cast<float4*>(&C[(size_t)row * ldc + c0]) =
            make_float4(siluf(g4.x) * va, siluf(g4.y) * vb,
                        siluf(g4.z) * vc, siluf(g4.w) * vd);
    } else {
        int   t = tok[row];
        float w = tw[row];
        float* ob = outp + (size_t)t * out_ld + c0;
        atomicAdd(ob + 0, w * va);
        atomicAdd(ob + 1, w * vb);
        atomicAdd(ob + 2, w * vc);
        atomicAdd(ob + 3, w * vd);
    }
}

// ------------------------------ core GEMM body ------------------------------
// C[M,N] = A[M,K] * B.  BKMAJ: B stored [N,K] (k contiguous);
//                      !BKMAJ: B stored [K,N] (n contiguous).
// GATHER: A rows indirected through gidx.
template <int EPI, bool GATHER, bool BKMAJ>
__device__ __forceinline__ void gemm_body(
    const float* __restrict__ A, int lda, const int* __restrict__ gidx,
    const float* __restrict__ B, int ldb,
    float* __restrict__ C, int ldc,
    const float* __restrict__ other,
    const int* __restrict__ tok, const float* __restrict__ tw,
    float* __restrict__ outp, int out_ld,
    int M, int K, int m0, int n0)
{
    __shared__ __align__(16) float As[2][BK][AS_LD];
    __shared__ __align__(16) float Bs[2][BK][BS_LD];

    const int tid = threadIdx.x;
    const int tx  = tid & 15;   // 16 n-groups of 4 cols
    const int ty  = tid >> 4;   // 16 m-groups of 8 rows

    // A loader: float4 along k, 2 rows per thread
    const int la_k = (tid & 3) * 4;
    const int la_m = tid >> 2;
    const float* aP[2];
    bool aV[2];
#pragma unroll
    for (int r = 0; r < 2; ++r) {
        int  mloc = la_m + 64 * r;
        int  row  = m0 + mloc;
        bool v    = (row < M);
        aV[r] = v;
        int g = 0;
        if (v) g = GATHER ? gidx[row] : row;
        aP[r] = A + (size_t)g * lda + la_k;
    }

    // B loader
    const float* bP;
    int lb_k, lb_n;
    if (BKMAJ) {
        lb_k = (tid & 3) * 4;
        lb_n = tid >> 2;
        bP = B + (size_t)(n0 + lb_n) * ldb + lb_k;
    } else {
        lb_n = (tid & 15) * 4;
        lb_k = tid >> 4;
        bP = B + (size_t)lb_k * ldb + n0 + lb_n;
    }

    u64 acc[4][4];
#pragma unroll
    for (int p = 0; p < 4; ++p)
#pragma unroll
        for (int j = 0; j < 4; ++j) acc[p][j] = 0ULL;

    const int ktiles = K / BK;
    float4 aR[2], bR;

    // prefetch tile 0
#pragma unroll
    for (int r = 0; r < 2; ++r)
        aR[r] = aV[r] ? *reinterpret_cast<const float4*>(aP[r])
                      : make_float4(0.f, 0.f, 0.f, 0.f);
    bR = *reinterpret_cast<const float4*>(bP);

#pragma unroll
    for (int r = 0; r < 2; ++r) {
        As[0][la_k + 0][la_m + 64 * r] = aR[r].x;
        As[0][la_k + 1][la_m + 64 * r] = aR[r].y;
        As[0][la_k + 2][la_m + 64 * r] = aR[r].z;
        As[0][la_k + 3][la_m + 64 * r] = aR[r].w;
    }
    if (BKMAJ) {
        Bs[0][lb_k + 0][lb_n] = bR.x;
        Bs[0][lb_k + 1][lb_n] = bR.y;
        Bs[0][lb_k + 2][lb_n] = bR.z;
        Bs[0][lb_k + 3][lb_n] = bR.w;
    } else {
        *reinterpret_cast<float4*>(&Bs[0][lb_k][lb_n]) = bR;
    }
    __syncthreads();

    int buf = 0;
    for (int kt = 0; kt < ktiles; ++kt) {
        const bool has = (kt + 1 < ktiles);
        if (has) {
            const int kpos = (kt + 1) * BK;
#pragma unroll
            for (int r = 0; r < 2; ++r)
                aR[r] = aV[r] ? *reinterpret_cast<const float4*>(aP[r] + kpos)
                              : make_float4(0.f, 0.f, 0.f, 0.f);
            bR = BKMAJ ? *reinterpret_cast<const float4*>(bP + kpos)
                       : *reinterpret_cast<const float4*>(bP + (size_t)kpos * ldb);
        }

#pragma unroll
        for (int kk = 0; kk < BK; ++kk) {
            float4 b4 = *reinterpret_cast<const float4*>(&Bs[buf][kk][tx * 4]);
            u64 br0 = pack2(b4.x, b4.x);
            u64 br1 = pack2(b4.y, b4.y);
            u64 br2 = pack2(b4.z, b4.z);
            u64 br3 = pack2(b4.w, b4.w);
            const u64* ap = reinterpret_cast<const u64*>(&As[buf][kk][ty * 8]);
            u64 a0 = ap[0], a1 = ap[1], a2 = ap[2], a3 = ap[3];
            acc[0][0] = ffma2(a0, br0, acc[0][0]);
            acc[0][1] = ffma2(a0, br1, acc[0][1]);
            acc[0][2] = ffma2(a0, br2, acc[0][2]);
            acc[0][3] = ffma2(a0, br3, acc[0][3]);
            acc[1][0] = ffma2(a1, br0, acc[1][0]);
            acc[1][1] = ffma2(a1, br1, acc[1][1]);
            acc[1][2] = ffma2(a1, br2, acc[1][2]);
            acc[1][3] = ffma2(a1, br3, acc[1][3]);
            acc[2][0] = ffma2(a2, br0, acc[2][0]);
            acc[2][1] = ffma2(a2, br1, acc[2][1]);
            acc[2][2] = ffma2(a2, br2, acc[2][2]);
            acc[2][3] = ffma2(a2, br3, acc[2][3]);
            acc[3][0] = ffma2(a3, br0, acc[3][0]);
            acc[3][1] = ffma2(a3, br1, acc[3][1]);
            acc[3][2] = ffma2(a3, br2, acc[3][2]);
            acc[3][3] = ffma2(a3, br3, acc[3][3]);
        }

        if (has) {
            const int nb = buf ^ 1;
#pragma unroll
            for (int r = 0; r < 2; ++r) {
                As[nb][la_k + 0][la_m + 64 * r] = aR[r].x;
                As[nb][la_k + 1][la_m + 64 * r] = aR[r].y;
                As[nb][la_k + 2][la_m + 64 * r] = aR[r].z;
                As[nb][la_k + 3][la_m + 64 * r] = aR[r].w;
            }
            if (BKMAJ) {
                Bs[nb][lb_k + 0][lb_n] = bR.x;
                Bs[nb][lb_k + 1][lb_n] = bR.y;
                Bs[nb][lb_k + 2][lb_n] = bR.z;
                Bs[nb][lb_k + 3][lb_n] = bR.w;
            } else {
                *reinterpret_cast<float4*>(&Bs[nb][lb_k][lb_n]) = bR;
            }
        }
        __syncthreads();
        buf ^= 1;
    }

    const int c0 = n0 + tx * 4;
#pragma unroll
    for (int p = 0; p < 4; ++p) {
        float2 v0 = unpack2(acc[p][0]);
        float2 v1 = unpack2(acc[p][1]);
        float2 v2 = unpack2(acc[p][2]);
        float2 v3 = unpack2(acc[p][3]);
        int r0 = m0 + ty * 8 + 2 * p;
        epi_row<EPI>(r0,     M, c0, v0.x, v1.x, v2.x, v3.x, C, ldc, other, tok, tw, outp, out_ld);
        epi_row<EPI>(r0 + 1, M, c0, v0.y, v1.y, v2.y, v3.y, C, ldc, other, tok, tw, outp, out_ld);
    }
}

// ------------------------------ small kernels -------------------------------
__global__ void k_init() {
    if (threadIdx.x < NE) g_counts[threadIdx.x] = 0;
}

__global__ void __launch_bounds__(128) k_router(const float* __restrict__ x,
                                                const float* __restrict__ rw) {
    int t    = blockIdx.x;
    int tid  = threadIdx.x;
    int w    = tid >> 5;
    int lane = tid & 31;
    const float* xr = x + (size_t)t * DIMD;
    __shared__ float sl[NE];

    for (int e = w; e < NE; e += 4) {
        const float* we = rw + (size_t)e * DIMD;
        float s = 0.f;
        for (int d = lane; d < DIMD; d += 32) s = fmaf(xr[d], we[d], s);
#pragma unroll
        for (int o = 16; o > 0; o >>= 1) s += __shfl_xor_sync(0xFFFFFFFFu, s, o);
        if (lane == 0) sl[e] = s;
    }
    __syncthreads();

    if (tid == 0) {
        int i0 = 0; float v0 = sl[0];
#pragma unroll
        for (int e = 1; e < NE; ++e)
            if (sl[e] > v0) { v0 = sl[e]; i0 = e; }
        int i1 = -1; float v1 = -3.0e38f;
#pragma unroll
        for (int e = 0; e < NE; ++e)
            if (e != i0 && sl[e] > v1) { v1 = sl[e]; i1 = e; }
        float s0 = 1.f / (1.f + expf(v1 - v0));   // stable 2-way softmax
        float s1 = 1.f - s0;
        g_top_idx[2 * t]     = i0;
        g_top_idx[2 * t + 1] = i1;
        g_top_w[2 * t]       = s0;
        g_top_w[2 * t + 1]   = s1;
        atomicAdd(&g_counts[i0], 1);
        atomicAdd(&g_counts[i1], 1);
    }
}

__global__ void k_offsets() {
    if (threadIdx.x == 0 && blockIdx.x == 0) {
        int s = 0;
#pragma unroll
        for (int e = 0; e < NE; ++e) {
            g_offsets[e] = s;
            g_pos[e]     = s;
            s += g_counts[e];
        }
        g_offsets[NE] = s;
    }
}

__global__ void k_scatter() {
    int i = blockIdx.x * blockDim.x + threadIdx.x;
    if (i < T_TOK * 2) {
        int e = g_top_idx[i];
        int p = atomicAdd(&g_pos[e], 1);
        g_tok[p]  = i >> 1;
        g_tokw[p] = g_top_w[i];
    }
}

// ------------------------------ GEMM wrappers -------------------------------
__global__ void __launch_bounds__(NTHR, 2) k_w1(const float* __restrict__ x,
                                                const float* __restrict__ w1) {
    gemm_body<0, false, true>(x, DIMD, nullptr, w1, DIMD, g_bufA, SHH, nullptr,
                              nullptr, nullptr, nullptr, 0,
                              T_TOK, DIMD, blockIdx.y * BM, blockIdx.x * BN);
}
__global__ void __launch_bounds__(NTHR, 2) k_w3(const float* __restrict__ x,
                                                const float* __restrict__ w3) {
    gemm_body<1, false, true>(x, DIMD, nullptr, w3, DIMD, g_bufB, SHH, g_bufA,
                              nullptr, nullptr, nullptr, 0,
                              T_TOK, DIMD, blockIdx.y * BM, blockIdx.x * BN);
}
__global__ void __launch_bounds__(NTHR, 2) k_w2(const float* __restrict__ w2,
                                                float* __restrict__ out) {
    gemm_body<0, false, true>(g_bufB, SHH, nullptr, w2, SHH, out, DIMD, nullptr,
                              nullptr, nullptr, nullptr, 0,
                              T_TOK, SHH, blockIdx.y * BM, blockIdx.x * BN);
}
__global__ void __launch_bounds__(NTHR, 2) k_gate(const float* __restrict__ x,
                                                  const float* __restrict__ gp) {
    int e   = blockIdx.z;
    int off = g_offsets[e];
    int ne  = g_offsets[e + 1] - off;
    int m0  = blockIdx.y * BM;
    if (m0 >= ne) return;
    gemm_body<0, true, false>(x, DIMD, g_tok + off,
                              gp + (size_t)e * DIMD * HH, HH,
                              g_bufA + (size_t)off * HH, HH, nullptr,
                              nullptr, nullptr, nullptr, 0,
                              ne, DIMD, m0, blockIdx.x * BN);
}
__global__ void __launch_bounds__(NTHR, 2) k_up(const float* __restrict__ x,
                                                const float* __restrict__ up) {
    int e   = blockIdx.z;
    int off = g_offsets[e];
    int ne  = g_offsets[e + 1] - off;
    int m0  = blockIdx.y * BM;
    if (m0 >= ne) return;
    gemm_body<1, true, false>(x, DIMD, g_tok + off,
                              up + (size_t)e * DIMD * HH, HH,
                              g_bufB + (size_t)off * HH, HH,
                              g_bufA + (size_t)off * HH,
                              nullptr, nullptr, nullptr, 0,
                              ne, DIMD, m0, blockIdx.x * BN);
}
__global__ void __launch_bounds__(NTHR, 2) k_down(const float* __restrict__ dp,
                                                  float* __restrict__ out) {
    int e   = blockIdx.z;
    int off = g_offsets[e];
    int ne  = g_offsets[e + 1] - off;
    int m0  = blockIdx.y * BM;
    if (m0 >= ne) return;
    gemm_body<2, false, false>(g_bufB + (size_t)off * HH, HH, nullptr,
                               dp + (size_t)e * HH * DIMD, DIMD,
                               nullptr, 0, nullptr,
                               g_tok + off, g_tokw + off, out, DIMD,
                               ne, HH, m0, blockIdx.x * BN);
}

// ------------------------------ entry point ---------------------------------
extern "C" void kernel_launch(void* const* d_in, const int* in_sizes, int n_in,
                              void* d_out, int out_size) {
    (void)in_sizes; (void)n_in; (void)out_size;
    const float* x  = (const float*)d_in[0];
    const float* rw = (const float*)d_in[1];
    const float* gp = (const float*)d_in[2];
    const float* up = (const float*)d_in[3];
    const float* dp = (const float*)d_in[4];
    const float* w1 = (const float*)d_in[5];
    const float* w2 = (const float*)d_in[6];
    const float* w3 = (const float*)d_in[7];
    float* out = (float*)d_out;

    // Router + grouping
    k_init<<<1, 32>>>();
    k_router<<<T_TOK, 128>>>(x, rw);
    k_offsets<<<1, 1>>>();
    k_scatter<<<(T_TOK * 2 + 255) / 256, 256>>>();

    // Shared FFN: w1 -> w3 (silu fuse) -> w2 (writes ALL of out)
    dim3 gs(SHH / BN, T_TOK / BM);           // 32 x 64
    k_w1<<<gs, NTHR>>>(x, w1);
    k_w3<<<gs, NTHR>>>(x, w3);
    dim3 gs2(DIMD / BN, T_TOK / BM);         // 64 x 64
    k_w2<<<gs2, NTHR>>>(w2, out);

    // Experts: gate -> up (silu fuse) -> down (atomic combine on top of out)
    dim3 ge(HH / BN, (T_TOK + BM - 1) / BM, NE);    // 16 x 64 x 8
    k_gate<<<ge, NTHR>>>(x, gp);
    k_up<<<ge, NTHR>>>(x, up);
    dim3 gd(DIMD / BN, (T_TOK + BM - 1) / BM, NE);  // 64 x 64 x 8
    k_down<<<gd, NTHR>>>(dp, out);
}

// round 15
// speedup vs baseline: 1.3225x; 1.3225x over previous
#include <cuda_runtime.h>
#include <cuda_bf16.h>
#include <math.h>
#include <stdint.h>

#define T_TOK 8192
#define DIMD  4096
#define NE    8
#define HH    1024
#define SHH   2048

// ---- mma GEMM tiling ----
#define BMT 128
#define BNT 128
#define BKT 16
#define AH_OFF 0
#define AL_OFF 4096
#define BH_OFF 8192
#define BL_OFF 13312
#define STG    18432                  // per-stage bytes
#define DSMEM  (2 * STG)              // 36864 < 48KB default

typedef __nv_bfloat16 bf16;

// ------------------------------ device scratch (same footprint as R10) ------
__device__ int   g_counts[NE];
__device__ int   g_offsets[NE + 1];
__device__ int   g_pos[NE];
__device__ int   g_top_idx[T_TOK * 2];
__device__ float g_top_w[T_TOK * 2];
__device__ int   g_tok[T_TOK * 2];
__device__ float g_tokw[T_TOK * 2];
__device__ float g_bufA[(size_t)T_TOK * 2 * HH];   // 64 MB fp32
__device__ float g_bufB[(size_t)T_TOK * 2 * HH];   // 64 MB fp32

// ------------------------------ helpers -------------------------------------
__device__ __forceinline__ void mma16816(float* c, const uint32_t* a,
                                         uint32_t b0, uint32_t b1) {
    asm volatile(
        "mma.sync.aligned.m16n8k16.row.col.f32.bf16.bf16.f32 "
        "{%0,%1,%2,%3}, {%4,%5,%6,%7}, {%8,%9}, {%0,%1,%2,%3};"
        : "+f"(c[0]), "+f"(c[1]), "+f"(c[2]), "+f"(c[3])
        : "r"(a[0]), "r"(a[1]), "r"(a[2]), "r"(a[3]), "r"(b0), "r"(b1));
}

// split two fp32 into packed-bf16 hi pair and lo (residual) pair
__device__ __forceinline__ void split2(float a, float b,
                                       uint32_t& h, uint32_t& l) {
    __nv_bfloat16 ha = __float2bfloat16(a), hb = __float2bfloat16(b);
    float la = a - __bfloat162float(ha);
    float lb = b - __bfloat162float(hb);
    __nv_bfloat16 xa = __float2bfloat16(la), xb = __float2bfloat16(lb);
    uint16_t uha, uhb, ula, ulb;
    memcpy(&uha, &ha, 2); memcpy(&uhb, &hb, 2);
    memcpy(&ula, &xa, 2); memcpy(&ulb, &xb, 2);
    h = (uint32_t)uha | ((uint32_t)uhb << 16);
    l = (uint32_t)ula | ((uint32_t)ulb << 16);
}

__device__ __forceinline__ float siluf(float x) { return x / (1.0f + __expf(-x)); }

// ------------------------------ core mma GEMM -------------------------------
// C tile (m0,n0) of C[M,N] = A[M,K] @ B^T.
// A: fp32 [rows][K] (lda), optionally gathered.
// B: fp32; BKMAJ: [N][K] (ldb=K-stride); !BKMAJ: [K][N] (ldb=N-stride).
// Inputs are split to bf16 hi/lo on the fly; bf16x3 passes; fp32 accum.
// EPI 0: Cf[row*ldc+c] = v
// EPI 1: Hf[row*ldc+c] = silu(other[row*ldc+c]) * v   (fp32 hid)
// EPI 2: atomicAdd(outp[tok[row]*DIMD + c], tw[row]*v)
template <int EPI, bool GATHER, bool BKMAJ>
__device__ __forceinline__ void mma_gemm(
    const float* __restrict__ A, int lda, const int* __restrict__ gidx,
    const float* __restrict__ B, int ldb,
    float* __restrict__ Cf, int ldc, const float* __restrict__ other,
    float* __restrict__ Hf,
    const int* __restrict__ tok, const float* __restrict__ tw,
    float* __restrict__ outp,
    int M, int K, int m0, int n0)
{
    extern __shared__ __align__(16) char sm[];

    const int tid  = threadIdx.x;
    const int wid  = tid >> 5;
    const int lane = tid & 31;
    const int wm   = wid >> 1;        // 0..3
    const int wn   = wid & 1;         // 0..1
    const int g    = lane >> 2;       // 0..7
    const int t    = lane & 3;        // 0..3

    // ---- A loader: row ar, 8-float chunk ach ----
    const int ar  = tid >> 1;
    const int ach = tid & 1;
    const int ra  = m0 + ar;
    const bool av = ra < M;
    int gA = 0;
    if (av) gA = GATHER ? gidx[ra] : ra;
    const float* pA = A + (size_t)gA * lda + ach * 8;

    // ---- B loader ----
    int bn = 0, bch = 0, bk = 0, bnc = 0;
    const float* pB;
    if (BKMAJ) {
        bn  = tid >> 1; bch = tid & 1;
        pB = B + (size_t)(n0 + bn) * ldb + bch * 8;
    } else {
        bk  = tid >> 4; bnc = tid & 15;
        pB = B + (size_t)bk * ldb + n0 + bnc * 8;
    }

    float acc[2][8][4];
#pragma unroll
    for (int mi = 0; mi < 2; ++mi)
#pragma unroll
        for (int ni = 0; ni < 8; ++ni)
#pragma unroll
            for (int q = 0; q < 4; ++q) acc[mi][ni][q] = 0.f;

    const int Kt = K / BKT;
    float4 aU0, aU1, bU0, bU1;

    auto loadAB = [&](int k0) {
        if (av) {
            aU0 = *reinterpret_cast<const float4*>(pA + k0);
            aU1 = *reinterpret_cast<const float4*>(pA + k0 + 4);
        } else {
            aU0 = make_float4(0.f, 0.f, 0.f, 0.f);
            aU1 = make_float4(0.f, 0.f, 0.f, 0.f);
        }
        if (BKMAJ) {
            bU0 = *reinterpret_cast<const float4*>(pB + k0);
            bU1 = *reinterpret_cast<const float4*>(pB + k0 + 4);
        } else {
            const float* q = pB + (size_t)k0 * ldb;
            bU0 = *reinterpret_cast<const float4*>(q);
            bU1 = *reinterpret_cast<const float4*>(q + 4);
        }
    };

    auto storeAB = [&](char* st) {
        // A tiles: 32 B rows, STS.128 aligned
        uint32_t h[4], l[4];
        split2(aU0.x, aU0.y, h[0], l[0]);
        split2(aU0.z, aU0.w, h[1], l[1]);
        split2(aU1.x, aU1.y, h[2], l[2]);
        split2(aU1.z, aU1.w, h[3], l[3]);
        *reinterpret_cast<uint4*>(st + AH_OFF + ar * 32 + ach * 16) =
            make_uint4(h[0], h[1], h[2], h[3]);
        *reinterpret_cast<uint4*>(st + AL_OFF + ar * 32 + ach * 16) =
            make_uint4(l[0], l[1], l[2], l[3]);
        // B tiles: 40 B rows
        uint32_t bh[4], bl[4];
        split2(bU0.x, bU0.y, bh[0], bl[0]);
        split2(bU0.z, bU0.w, bh[1], bl[1]);
        split2(bU1.x, bU1.y, bh[2], bl[2]);
        split2(bU1.z, bU1.w, bh[3], bl[3]);
        if (BKMAJ) {
            char* d = st + BH_OFF + bn * 40 + bch * 16;
            *reinterpret_cast<uint2*>(d)     = make_uint2(bh[0], bh[1]);
            *reinterpret_cast<uint2*>(d + 8) = make_uint2(bh[2], bh[3]);
            d = st + BL_OFF + bn * 40 + bch * 16;
            *reinterpret_cast<uint2*>(d)     = make_uint2(bl[0], bl[1]);
            *reinterpret_cast<uint2*>(d + 8) = make_uint2(bl[2], bl[3]);
        } else {
            // transpose [k][n] -> [n][k] pairs via partner exchange (lane^16 = k^1)
            uint32_t ph[4], pl[4];
#pragma unroll
            for (int r4 = 0; r4 < 4; ++r4) {
                ph[r4] = __shfl_xor_sync(0xFFFFFFFFu, bh[r4], 16);
                pl[r4] = __shfl_xor_sync(0xFFFFFFFFu, bl[r4], 16);
            }
            const int kev = bk & ~1;
            uint32_t ow[8];
            char* dbase;
            if ((bk & 1) == 0) {         // even-k lanes build hi tile pairs
#pragma unroll
                for (int r4 = 0; r4 < 4; ++r4) {
                    ow[2 * r4]     = __byte_perm(bh[r4], ph[r4], 0x5410);
                    ow[2 * r4 + 1] = __byte_perm(bh[r4], ph[r4], 0x7632);
                }
                dbase = st + BH_OFF + kev * 2;
            } else {                      // odd-k lanes build lo tile pairs
#pragma unroll
                for (int r4 = 0; r4 < 4; ++r4) {
                    ow[2 * r4]     = __byte_perm(pl[r4], bl[r4], 0x5410);
                    ow[2 * r4 + 1] = __byte_perm(pl[r4], bl[r4], 0x7632);
                }
                dbase = st + BL_OFF + kev * 2;
            }
#pragma unroll
            for (int j = 0; j < 8; ++j)
                *reinterpret_cast<uint32_t*>(dbase + (bnc * 8 + j) * 40) = ow[j];
        }
    };

    // prefetch k-tile 0
    loadAB(0);
    storeAB(sm);
    __syncthreads();

    int buf = 0;
    for (int kt = 0; kt < Kt; ++kt) {
        const bool has = (kt + 1 < Kt);
        if (has) loadAB((kt + 1) * BKT);

        // ---- compute one k16 ----
        {
            const char* base = sm + buf * STG;
            const int cb = 4 * t;
            uint32_t afr[2][2][4];
#pragma unroll
            for (int mi = 0; mi < 2; ++mi)
#pragma unroll
                for (int p = 0; p < 2; ++p) {
                    const char* q = base + (p ? AL_OFF : AH_OFF) +
                                    (wm * 32 + mi * 16 + g) * 32 + cb;
                    afr[mi][p][0] = *(const uint32_t*)q;
                    afr[mi][p][1] = *(const uint32_t*)(q + 8 * 32);
                    afr[mi][p][2] = *(const uint32_t*)(q + 16);
                    afr[mi][p][3] = *(const uint32_t*)(q + 8 * 32 + 16);
                }
#pragma unroll
            for (int ni = 0; ni < 8; ++ni) {
                const char* qh = base + BH_OFF +
                                 (wn * 64 + ni * 8 + g) * 40 + cb;
                uint32_t bh0 = *(const uint32_t*)qh;
                uint32_t bh1 = *(const uint32_t*)(qh + 16);
                uint32_t bl0 = *(const uint32_t*)(qh + (BL_OFF - BH_OFF));
                uint32_t bl1 = *(const uint32_t*)(qh + (BL_OFF - BH_OFF) + 16);
#pragma unroll
                for (int mi = 0; mi < 2; ++mi) {
                    mma16816(acc[mi][ni], afr[mi][0], bh0, bh1);
                    mma16816(acc[mi][ni], afr[mi][0], bl0, bl1);
                    mma16816(acc[mi][ni], afr[mi][1], bh0, bh1);
                }
            }
        }

        if (has) storeAB(sm + (buf ^ 1) * STG);
        __syncthreads();
        buf ^= 1;
    }

    // ------------------------------ epilogue ------------------------------
#pragma unroll
    for (int mi = 0; mi < 2; ++mi) {
        const int row0 = m0 + wm * 32 + mi * 16 + g;
        const int row1 = row0 + 8;
        const bool e0 = row0 < M, e1 = row1 < M;
        int tk0 = 0, tk1 = 0; float wt0 = 0.f, wt1 = 0.f;
        if (EPI == 2) {
            if (e0) { tk0 = tok[row0]; wt0 = tw[row0]; }
            if (e1) { tk1 = tok[row1]; wt1 = tw[row1]; }
        }
#pragma unroll
        for (int ni = 0; ni < 8; ++ni) {
            const float* c = acc[mi][ni];
            const int col = n0 + wn * 64 + ni * 8 + 2 * t;
            if (EPI == 0) {
                if (e0) *reinterpret_cast<float2*>(&Cf[(size_t)row0 * ldc + col]) =
                            make_float2(c[0], c[1]);
                if (e1) *reinterpret_cast<float2*>(&Cf[(size_t)row1 * ldc + col]) =
                            make_float2(c[2], c[3]);
            } else if (EPI == 1) {
                if (e0) {
                    float2 gs = *reinterpret_cast<const float2*>(
                                    &other[(size_t)row0 * ldc + col]);
                    *reinterpret_cast<float2*>(&Hf[(size_t)row0 * ldc + col]) =
                        make_float2(siluf(gs.x) * c[0], siluf(gs.y) * c[1]);
                }
                if (e1) {
                    float2 gs = *reinterpret_cast<const float2*>(
                                    &other[(size_t)row1 * ldc + col]);
                    *reinterpret_cast<float2*>(&Hf[(size_t)row1 * ldc + col]) =
                        make_float2(siluf(gs.x) * c[2], siluf(gs.y) * c[3]);
                }
            } else {
                if (e0) {
                    float* ob = outp + (size_t)tk0 * DIMD + col;
                    atomicAdd(ob + 0, wt0 * c[0]);
                    atomicAdd(ob + 1, wt0 * c[1]);
                }
                if (e1) {
                    float* ob = outp + (size_t)tk1 * DIMD + col;
                    atomicAdd(ob + 0, wt1 * c[2]);
                    atomicAdd(ob + 1, wt1 * c[3]);
                }
            }
        }
    }
}

// ------------------------------ GEMM wrappers -------------------------------
__global__ void __launch_bounds__(256) mk_w1(const float* __restrict__ x,
                                             const float* __restrict__ w1) {
    mma_gemm<0, false, true>(x, DIMD, nullptr, w1, DIMD,
                             g_bufA, SHH, nullptr, nullptr,
                             nullptr, nullptr, nullptr,
                             T_TOK, DIMD, blockIdx.y * BMT, blockIdx.x * BNT);
}
__global__ void __launch_bounds__(256) mk_w3(const float* __restrict__ x,
                                             const float* __restrict__ w3) {
    mma_gemm<1, false, true>(x, DIMD, nullptr, w3, DIMD,
                             nullptr, SHH, g_bufA, g_bufB,
                             nullptr, nullptr, nullptr,
                             T_TOK, DIMD, blockIdx.y * BMT, blockIdx.x * BNT);
}
__global__ void __launch_bounds__(256) mk_w2(const float* __restrict__ w2,
                                             float* __restrict__ out) {
    mma_gemm<0, false, true>(g_bufB, SHH, nullptr, w2, SHH,
                             out, DIMD, nullptr, nullptr,
                             nullptr, nullptr, nullptr,
                             T_TOK, SHH, blockIdx.y * BMT, blockIdx.x * BNT);
}
__global__ void __launch_bounds__(256) mk_gate(const float* __restrict__ x,
                                               const float* __restrict__ gp) {
    int e = blockIdx.z;
    int off = g_offsets[e];
    int ne  = g_offsets[e + 1] - off;
    int m0  = blockIdx.y * BMT;
    if (m0 >= ne) return;
    mma_gemm<0, true, false>(x, DIMD, g_tok + off,
                             gp + (size_t)e * DIMD * HH, HH,
                             g_bufA + (size_t)off * HH, HH, nullptr, nullptr,
                             nullptr, nullptr, nullptr,
                             ne, DIMD, m0, blockIdx.x * BNT);
}
__global__ void __launch_bounds__(256) mk_up(const float* __restrict__ x,
                                             const float* __restrict__ up) {
    int e = blockIdx.z;
    int off = g_offsets[e];
    int ne  = g_offsets[e + 1] - off;
    int m0  = blockIdx.y * BMT;
    if (m0 >= ne) return;
    mma_gemm<1, true, false>(x, DIMD, g_tok + off,
                             up + (size_t)e * DIMD * HH, HH,
                             nullptr, HH, g_bufA + (size_t)off * HH,
                             g_bufB + (size_t)off * HH,
                             nullptr, nullptr, nullptr,
                             ne, DIMD, m0, blockIdx.x * BNT);
}
__global__ void __launch_bounds__(256) mk_down(const float* __restrict__ dp,
                                               float* __restrict__ out) {
    int e = blockIdx.z;
    int off = g_offsets[e];
    int ne  = g_offsets[e + 1] - off;
    int m0  = blockIdx.y * BMT;
    if (m0 >= ne) return;
    mma_gemm<2, false, false>(g_bufB + (size_t)off * HH, HH, nullptr,
                              dp + (size_t)e * HH * DIMD, DIMD,
                              nullptr, 0, nullptr, nullptr,
                              g_tok + off, g_tokw + off, out,
                              ne, HH, m0, blockIdx.x * BNT);
}

// ------------------------------ router kernels ------------------------------
__global__ void k_init() {
    if (threadIdx.x < NE) g_counts[threadIdx.x] = 0;
}

__global__ void __launch_bounds__(128) k_router(const float* __restrict__ x,
                                                const float* __restrict__ rw) {
    int t    = blockIdx.x;
    int tid  = threadIdx.x;
    int w    = tid >> 5;
    int lane = tid & 31;
    const float* xr = x + (size_t)t * DIMD;
    __shared__ float sl[NE];

    for (int e = w; e < NE; e += 4) {
        const float* we = rw + (size_t)e * DIMD;
        float s = 0.f;
        for (int d = lane; d < DIMD; d += 32) s = fmaf(xr[d], we[d], s);
#pragma unroll
        for (int o = 16; o > 0; o >>= 1) s += __shfl_xor_sync(0xFFFFFFFFu, s, o);
        if (lane == 0) sl[e] = s;
    }
    __syncthreads();

    if (tid == 0) {
        int i0 = 0; float v0 = sl[0];
#pragma unroll
        for (int e = 1; e < NE; ++e)
            if (sl[e] > v0) { v0 = sl[e]; i0 = e; }
        int i1 = -1; float v1 = -3.0e38f;
#pragma unroll
        for (int e = 0; e < NE; ++e)
            if (e != i0 && sl[e] > v1) { v1 = sl[e]; i1 = e; }
        float s0 = 1.f / (1.f + expf(v1 - v0));
        float s1 = 1.f - s0;
        g_top_idx[2 * t]     = i0;
        g_top_idx[2 * t + 1] = i1;
        g_top_w[2 * t]       = s0;
        g_top_w[2 * t + 1]   = s1;
        atomicAdd(&g_counts[i0], 1);
        atomicAdd(&g_counts[i1], 1);
    }
}

__global__ void k_offsets() {
    if (threadIdx.x == 0 && blockIdx.x == 0) {
        int s = 0;
#pragma unroll
        for (int e = 0; e < NE; ++e) {
            g_offsets[e] = s;
            g_pos[e]     = s;
            s += g_counts[e];
        }
        g_offsets[NE] = s;
    }
}

__global__ void k_scatter() {
    int i = blockIdx.x * blockDim.x + threadIdx.x;
    if (i < T_TOK * 2) {
        int e = g_top_idx[i];
        int p = atomicAdd(&g_pos[e], 1);
        g_tok[p]  = i >> 1;
        g_tokw[p] = g_top_w[i];
    }
}

// ------------------------------ entry point ---------------------------------
extern "C" void kernel_launch(void* const* d_in, const int* in_sizes, int n_in,
                              void* d_out, int out_size) {
    (void)in_sizes; (void)n_in; (void)out_size;
    const float* x  = (const float*)d_in[0];
    const float* rw = (const float*)d_in[1];
    const float* gp = (const float*)d_in[2];
    const float* up = (const float*)d_in[3];
    const float* dp = (const float*)d_in[4];
    const float* w1 = (const float*)d_in[5];
    const float* w2 = (const float*)d_in[6];
    const float* w3 = (const float*)d_in[7];
    float* out = (float*)d_out;

    // Router + grouping
    k_init<<<1, 32>>>();
    k_router<<<T_TOK, 128>>>(x, rw);
    k_offsets<<<1, 1>>>();
    k_scatter<<<(T_TOK * 2 + 255) / 256, 256>>>();

    // Shared FFN: w1 -> w3 (silu fuse, fp32 hid) -> w2 (writes ALL of out)
    mk_w1<<<dim3(SHH / BNT, T_TOK / BMT), 256, DSMEM>>>(x, w1);
    mk_w3<<<dim3(SHH / BNT, T_TOK / BMT), 256, DSMEM>>>(x, w3);
    mk_w2<<<dim3(DIMD / BNT, T_TOK / BMT), 256, DSMEM>>>(w2, out);

    // Experts: gate -> up (silu fuse) -> down (atomic combine)
    mk_gate<<<dim3(HH / BNT, 2 * T_TOK / BMT, NE), 256, DSMEM>>>(x, gp);
    mk_up  <<<dim3(HH / BNT, 2 * T_TOK / BMT, NE), 256, DSMEM>>>(x, up);
    mk_down<<<dim3(DIMD / BNT, 2 * T_TOK / BMT, NE), 256, DSMEM>>>(dp, out);
}

// round 17
// speedup vs baseline: 1.4063x; 1.0634x over previous
#include <cuda_runtime.h>
#include <cuda_bf16.h>
#include <math.h>
#include <stdint.h>
#include <string.h>

#define T_TOK 8192
#define DIMD  4096
#define NE    8
#define HH    1024
#define SHH   2048

// ---- mma GEMM tiling ----
#define BMT 128
#define BNT 128
#define BKT 16
#define AH_OFF 0
#define AL_OFF 4096
#define BH_OFF 8192
#define BL_OFF 13312
#define STG    18432                  // per-stage bytes
#define DSMEM  (2 * STG)              // 36864 < 48KB default

typedef __nv_bfloat16 bf16;

// ------------------------------ device scratch (134 MB, proven) -------------
__device__ int   g_counts[NE];
__device__ int   g_offsets[NE + 1];
__device__ int   g_pos[NE];
__device__ int   g_top_idx[T_TOK * 2];
__device__ float g_top_w[T_TOK * 2];
__device__ int   g_tok[T_TOK * 2];
__device__ float g_tokw[T_TOK * 2];
__device__ float g_bufA[(size_t)T_TOK * 2 * HH];   // 64 MB fp32
__device__ float g_bufB[(size_t)T_TOK * 2 * HH];   // 64 MB fp32

// ------------------------------ helpers -------------------------------------
__device__ __forceinline__ void mma16816(float* c, const uint32_t* a,
                                         uint32_t b0, uint32_t b1) {
    asm volatile(
        "mma.sync.aligned.m16n8k16.row.col.f32.bf16.bf16.f32 "
        "{%0,%1,%2,%3}, {%4,%5,%6,%7}, {%8,%9}, {%0,%1,%2,%3};"
        : "+f"(c[0]), "+f"(c[1]), "+f"(c[2]), "+f"(c[3])
        : "r"(a[0]), "r"(a[1]), "r"(a[2]), "r"(a[3]), "r"(b0), "r"(b1));
}

// split two fp32 -> packed-bf16 hi pair + lo(residual) pair (a->low, b->high)
__device__ __forceinline__ void split2(float a, float b,
                                       uint32_t& h, uint32_t& l) {
    __nv_bfloat162 hp = __floats2bfloat162_rn(a, b);
    uint32_t hu; memcpy(&hu, &hp, 4);
    float fa = __uint_as_float(hu << 16);
    float fb = __uint_as_float(hu & 0xffff0000u);
    __nv_bfloat162 lp = __floats2bfloat162_rn(a - fa, b - fb);
    uint32_t lu; memcpy(&lu, &lp, 4);
    h = hu; l = lu;
}

__device__ __forceinline__ float siluf(float x) { return x / (1.0f + __expf(-x)); }

// ------------------------------ core mma GEMM -------------------------------
// C tile (m0,n0) of C[M,N] = A[M,K] @ B^T.
// A: fp32 [rows][K] (lda), optionally gathered.
// B: fp32; BKMAJ: [N][K] (ldb=K-stride); !BKMAJ: [K][N] (ldb=N-stride).
// Inputs are split to bf16 hi/lo on the fly; bf16x3 passes; fp32 accum.
// EPI 0: Cf[row*ldc+c] = v
// EPI 1: Hf[row*ldc+c] = silu(other[row*ldc+c]) * v   (fp32 hid)
// EPI 2: atomicAdd(outp[tok[row]*DIMD + c], tw[row]*v)
template <int EPI, bool GATHER, bool BKMAJ>
__device__ __forceinline__ void mma_gemm(
    const float* __restrict__ A, int lda, const int* __restrict__ gidx,
    const float* __restrict__ B, int ldb,
    float* __restrict__ Cf, int ldc, const float* __restrict__ other,
    float* __restrict__ Hf,
    const int* __restrict__ tok, const float* __restrict__ tw,
    float* __restrict__ outp,
    int M, int K, int m0, int n0)
{
    extern __shared__ __align__(16) char sm[];

    const int tid  = threadIdx.x;
    const int wid  = tid >> 5;
    const int lane = tid & 31;
    const int wm   = wid >> 1;        // 0..3
    const int wn   = wid & 1;         // 0..1
    const int g    = lane >> 2;
    const int t    = lane & 3;

    // ---- A loader: row ar, 8-float chunk ach ----
    const int ar  = tid >> 1;
    const int ach = tid & 1;
    const int ra  = m0 + ar;
    const bool av = ra < M;
    int gA = 0;
    if (av) gA = GATHER ? gidx[ra] : ra;
    const float* pA = A + (size_t)gA * lda + ach * 8;

    // ---- B loader ----
    int bn = 0, bch = 0, bk = 0, bnc = 0;
    const float* pB;
    if (BKMAJ) {
        bn  = tid >> 1; bch = tid & 1;
        pB = B + (size_t)(n0 + bn) * ldb + bch * 8;
    } else {
        bk  = tid >> 4; bnc = tid & 15;
        pB = B + (size_t)bk * ldb + n0 + bnc * 8;
    }

    float acc[2][8][4];
#pragma unroll
    for (int mi = 0; mi < 2; ++mi)
#pragma unroll
        for (int ni = 0; ni < 8; ++ni)
#pragma unroll
            for (int q = 0; q < 4; ++q) acc[mi][ni][q] = 0.f;

    const int Kt = K / BKT;
    float4 aU0, aU1, bU0, bU1;

    auto loadAB = [&](int k0) {
        if (av) {
            aU0 = *reinterpret_cast<const float4*>(pA + k0);
            aU1 = *reinterpret_cast<const float4*>(pA + k0 + 4);
        } else {
            aU0 = make_float4(0.f, 0.f, 0.f, 0.f);
            aU1 = make_float4(0.f, 0.f, 0.f, 0.f);
        }
        if (BKMAJ) {
            bU0 = *reinterpret_cast<const float4*>(pB + k0);
            bU1 = *reinterpret_cast<const float4*>(pB + k0 + 4);
        } else {
            const float* q = pB + (size_t)k0 * ldb;
            bU0 = *reinterpret_cast<const float4*>(q);
            bU1 = *reinterpret_cast<const float4*>(q + 4);
        }
    };

    auto storeAB = [&](char* st) {
        // A tiles: 32 B rows, STS.128 aligned
        uint32_t h[4], l[4];
        split2(aU0.x, aU0.y, h[0], l[0]);
        split2(aU0.z, aU0.w, h[1], l[1]);
        split2(aU1.x, aU1.y, h[2], l[2]);
        split2(aU1.z, aU1.w, h[3], l[3]);
        *reinterpret_cast<uint4*>(st + AH_OFF + ar * 32 + ach * 16) =
            make_uint4(h[0], h[1], h[2], h[3]);
        *reinterpret_cast<uint4*>(st + AL_OFF + ar * 32 + ach * 16) =
            make_uint4(l[0], l[1], l[2], l[3]);
        // B tiles: 40 B rows
        uint32_t bh[4], bl[4];
        split2(bU0.x, bU0.y, bh[0], bl[0]);
        split2(bU0.z, bU0.w, bh[1], bl[1]);
        split2(bU1.x, bU1.y, bh[2], bl[2]);
        split2(bU1.z, bU1.w, bh[3], bl[3]);
        if (BKMAJ) {
            char* d = st + BH_OFF + bn * 40 + bch * 16;
            *reinterpret_cast<uint2*>(d)     = make_uint2(bh[0], bh[1]);
            *reinterpret_cast<uint2*>(d + 8) = make_uint2(bh[2], bh[3]);
            d = st + BL_OFF + bn * 40 + bch * 16;
            *reinterpret_cast<uint2*>(d)     = make_uint2(bl[0], bl[1]);
            *reinterpret_cast<uint2*>(d + 8) = make_uint2(bl[2], bl[3]);
        } else {
            // transpose [k][n] -> [n][k] pairs via partner exchange (lane^16 = k^1)
            uint32_t ph[4], pl[4];
#pragma unroll
            for (int r4 = 0; r4 < 4; ++r4) {
                ph[r4] = __shfl_xor_sync(0xFFFFFFFFu, bh[r4], 16);
                pl[r4] = __shfl_xor_sync(0xFFFFFFFFu, bl[r4], 16);
            }
            const int kev = bk & ~1;
            uint32_t ow[8];
            char* dbase;
            if ((bk & 1) == 0) {          // even-k lanes build hi tile pairs
#pragma unroll
                for (int r4 = 0; r4 < 4; ++r4) {
                    ow[2 * r4]     = __byte_perm(bh[r4], ph[r4], 0x5410);
                    ow[2 * r4 + 1] = __byte_perm(bh[r4], ph[r4], 0x7632);
                }
                dbase = st + BH_OFF + kev * 2;
            } else {                       // odd-k lanes build lo tile pairs
#pragma unroll
                for (int r4 = 0; r4 < 4; ++r4) {
                    ow[2 * r4]     = __byte_perm(pl[r4], bl[r4], 0x5410);
                    ow[2 * r4 + 1] = __byte_perm(pl[r4], bl[r4], 0x7632);
                }
                dbase = st + BL_OFF + kev * 2;
            }
#pragma unroll
            for (int j = 0; j < 8; ++j)
                *reinterpret_cast<uint32_t*>(dbase + (bnc * 8 + j) * 40) = ow[j];
        }
    };

    // prefetch k-tile 0
    loadAB(0);
    storeAB(sm);
    __syncthreads();

    int buf = 0;
    for (int kt = 0; kt < Kt; ++kt) {
        const bool has = (kt + 1 < Kt);
        if (has) loadAB((kt + 1) * BKT);

        // ---- compute one k16 ----
        {
            const char* base = sm + buf * STG;
            const int cb = 4 * t;
            uint32_t afr[2][2][4];
#pragma unroll
            for (int mi = 0; mi < 2; ++mi)
#pragma unroll
                for (int p = 0; p < 2; ++p) {
                    const char* q = base + (p ? AL_OFF : AH_OFF) +
                                    (wm * 32 + mi * 16 + g) * 32 + cb;
                    afr[mi][p][0] = *(const uint32_t*)q;
                    afr[mi][p][1] = *(const uint32_t*)(q + 8 * 32);
                    afr[mi][p][2] = *(const uint32_t*)(q + 16);
                    afr[mi][p][3] = *(const uint32_t*)(q + 8 * 32 + 16);
                }
#pragma unroll
            for (int ni = 0; ni < 8; ++ni) {
                const char* qh = base + BH_OFF +
                                 (wn * 64 + ni * 8 + g) * 40 + cb;
                uint32_t bh0 = *(const uint32_t*)qh;
                uint32_t bh1 = *(const uint32_t*)(qh + 16);
                uint32_t bl0 = *(const uint32_t*)(qh + (BL_OFF - BH_OFF));
                uint32_t bl1 = *(const uint32_t*)(qh + (BL_OFF - BH_OFF) + 16);
#pragma unroll
                for (int mi = 0; mi < 2; ++mi) {
                    mma16816(acc[mi][ni], afr[mi][0], bh0, bh1);
                    mma16816(acc[mi][ni], afr[mi][0], bl0, bl1);
                    mma16816(acc[mi][ni], afr[mi][1], bh0, bh1);
                }
            }
        }

        if (has) storeAB(sm + (buf ^ 1) * STG);
        __syncthreads();
        buf ^= 1;
    }

    // ------------------------------ epilogue ------------------------------
#pragma unroll
    for (int mi = 0; mi < 2; ++mi) {
        const int row0 = m0 + wm * 32 + mi * 16 + g;
        const int row1 = row0 + 8;
        const bool e0 = row0 < M, e1 = row1 < M;
        int tk0 = 0, tk1 = 0; float wt0 = 0.f, wt1 = 0.f;
        if (EPI == 2) {
            if (e0) { tk0 = tok[row0]; wt0 = tw[row0]; }
            if (e1) { tk1 = tok[row1]; wt1 = tw[row1]; }
        }
#pragma unroll
        for (int ni = 0; ni < 8; ++ni) {
            const float* c = acc[mi][ni];
            const int col = n0 + wn * 64 + ni * 8 + 2 * t;
            if (EPI == 0) {
                if (e0) *reinterpret_cast<float2*>(&Cf[(size_t)row0 * ldc + col]) =
                            make_float2(c[0], c[1]);
                if (e1) *reinterpret_cast<float2*>(&Cf[(size_t)row1 * ldc + col]) =
                            make_float2(c[2], c[3]);
            } else if (EPI == 1) {
                if (e0) {
                    float2 gs = *reinterpret_cast<const float2*>(
                                    &other[(size_t)row0 * ldc + col]);
                    *reinterpret_cast<float2*>(&Hf[(size_t)row0 * ldc + col]) =
                        make_float2(siluf(gs.x) * c[0], siluf(gs.y) * c[1]);
                }
                if (e1) {
                    float2 gs = *reinterpret_cast<const float2*>(
                                    &other[(size_t)row1 * ldc + col]);
                    *reinterpret_cast<float2*>(&Hf[(size_t)row1 * ldc + col]) =
                        make_float2(siluf(gs.x) * c[2], siluf(gs.y) * c[3]);
                }
            } else {
                if (e0) {
                    float* ob = outp + (size_t)tk0 * DIMD + col;
                    atomicAdd(ob + 0, wt0 * c[0]);
                    atomicAdd(ob + 1, wt0 * c[1]);
                }
                if (e1) {
                    float* ob = outp + (size_t)tk1 * DIMD + col;
                    atomicAdd(ob + 0, wt1 * c[2]);
                    atomicAdd(ob + 1, wt1 * c[3]);
                }
            }
        }
    }
}

// ------------------------------ GEMM wrappers (2 CTAs/SM) -------------------
__global__ void __launch_bounds__(256, 2) mk_w1(const float* __restrict__ x,
                                                const float* __restrict__ w1) {
    mma_gemm<0, false, true>(x, DIMD, nullptr, w1, DIMD,
                             g_bufA, SHH, nullptr, nullptr,
                             nullptr, nullptr, nullptr,
                             T_TOK, DIMD, blockIdx.y * BMT, blockIdx.x * BNT);
}
__global__ void __launch_bounds__(256, 2) mk_w3(const float* __restrict__ x,
                                                const float* __restrict__ w3) {
    mma_gemm<1, false, true>(x, DIMD, nullptr, w3, DIMD,
                             nullptr, SHH, g_bufA, g_bufB,
                             nullptr, nullptr, nullptr,
                             T_TOK, DIMD, blockIdx.y * BMT, blockIdx.x * BNT);
}
__global__ void __launch_bounds__(256, 2) mk_w2(const float* __restrict__ w2,
                                                float* __restrict__ out) {
    mma_gemm<0, false, true>(g_bufB, SHH, nullptr, w2, SHH,
                             out, DIMD, nullptr, nullptr,
                             nullptr, nullptr, nullptr,
                             T_TOK, SHH, blockIdx.y * BMT, blockIdx.x * BNT);
}
__global__ void __launch_bounds__(256, 2) mk_gate(const float* __restrict__ x,
                                                  const float* __restrict__ gp) {
    int e = blockIdx.z;
    int off = g_offsets[e];
    int ne  = g_offsets[e + 1] - off;
    int m0  = blockIdx.y * BMT;
    if (m0 >= ne) return;
    mma_gemm<0, true, false>(x, DIMD, g_tok + off,
                             gp + (size_t)e * DIMD * HH, HH,
                             g_bufA + (size_t)off * HH, HH, nullptr, nullptr,
                             nullptr, nullptr, nullptr,
                             ne, DIMD, m0, blockIdx.x * BNT);
}
__global__ void __launch_bounds__(256, 2) mk_up(const float* __restrict__ x,
                                                const float* __restrict__ up) {
    int e = blockIdx.z;
    int off = g_offsets[e];
    int ne  = g_offsets[e + 1] - off;
    int m0  = blockIdx.y * BMT;
    if (m0 >= ne) return;
    mma_gemm<1, true, false>(x, DIMD, g_tok + off,
                             up + (size_t)e * DIMD * HH, HH,
                             nullptr, HH, g_bufA + (size_t)off * HH,
                             g_bufB + (size_t)off * HH,
                             nullptr, nullptr, nullptr,
                             ne, DIMD, m0, blockIdx.x * BNT);
}
__global__ void __launch_bounds__(256, 2) mk_down(const float* __restrict__ dp,
                                                  float* __restrict__ out) {
    int e = blockIdx.z;
    int off = g_offsets[e];
    int ne  = g_offsets[e + 1] - off;
    int m0  = blockIdx.y * BMT;
    if (m0 >= ne) return;
    mma_gemm<2, false, false>(g_bufB + (size_t)off * HH, HH, nullptr,
                              dp + (size_t)e * HH * DIMD, DIMD,
                              nullptr, 0, nullptr, nullptr,
                              g_tok + off, g_tokw + off, out,
                              ne, HH, m0, blockIdx.x * BNT);
}

// ------------------------------ router kernels ------------------------------
__global__ void k_init() {
    if (threadIdx.x < NE) g_counts[threadIdx.x] = 0;
}

__global__ void __launch_bounds__(128) k_router(const float* __restrict__ x,
                                                const float* __restrict__ rw) {
    int t    = blockIdx.x;
    int tid  = threadIdx.x;
    int w    = tid >> 5;
    int lane = tid & 31;
    const float* xr = x + (size_t)t * DIMD;
    __shared__ float sl[NE];

    for (int e = w; e < NE; e += 4) {
        const float* we = rw + (size_t)e * DIMD;
        float s = 0.f;
        for (int d = lane; d < DIMD; d += 32) s = fmaf(xr[d], we[d], s);
#pragma unroll
        for (int o = 16; o > 0; o >>= 1) s += __shfl_xor_sync(0xFFFFFFFFu, s, o);
        if (lane == 0) sl[e] = s;
    }
    __syncthreads();

    if (tid == 0) {
        int i0 = 0; float v0 = sl[0];
#pragma unroll
        for (int e = 1; e < NE; ++e)
            if (sl[e] > v0) { v0 = sl[e]; i0 = e; }
        int i1 = -1; float v1 = -3.0e38f;
#pragma unroll
        for (int e = 0; e < NE; ++e)
            if (e != i0 && sl[e] > v1) { v1 = sl[e]; i1 = e; }
        float s0 = 1.f / (1.f + expf(v1 - v0));
        float s1 = 1.f - s0;
        g_top_idx[2 * t]     = i0;
        g_top_idx[2 * t + 1] = i1;
        g_top_w[2 * t]       = s0;
        g_top_w[2 * t + 1]   = s1;
        atomicAdd(&g_counts[i0], 1);
        atomicAdd(&g_counts[i1], 1);
    }
}

__global__ void k_offsets() {
    if (threadIdx.x == 0 && blockIdx.x == 0) {
        int s = 0;
#pragma unroll
        for (int e = 0; e < NE; ++e) {
            g_offsets[e] = s;
            g_pos[e]     = s;
            s += g_counts[e];
        }
        g_offsets[NE] = s;
    }
}

__global__ void k_scatter() {
    int i = blockIdx.x * blockDim.x + threadIdx.x;
    if (i < T_TOK * 2) {
        int e = g_top_idx[i];
        int p = atomicAdd(&g_pos[e], 1);
        g_tok[p]  = i >> 1;
        g_tokw[p] = g_top_w[i];
    }
}

// ------------------------------ entry point ---------------------------------
extern "C" void kernel_launch(void* const* d_in, const int* in_sizes, int n_in,
                              void* d_out, int out_size) {
    (void)in_sizes; (void)n_in; (void)out_size;
    const float* x  = (const float*)d_in[0];
    const float* rw = (const float*)d_in[1];
    const float* gp = (const float*)d_in[2];
    const float* up = (const float*)d_in[3];
    const float* dp = (const float*)d_in[4];
    const float* w1 = (const float*)d_in[5];
    const float* w2 = (const float*)d_in[6];
    const float* w3 = (const float*)d_in[7];
    float* out = (float*)d_out;

    // Router + grouping
    k_init<<<1, 32>>>();
    k_router<<<T_TOK, 128>>>(x, rw);
    k_offsets<<<1, 1>>>();
    k_scatter<<<(T_TOK * 2 + 255) / 256, 256>>>();

    // Shared FFN: w1 -> w3 (silu fuse, fp32 hid) -> w2 (writes ALL of out)
    mk_w1<<<dim3(SHH / BNT, T_TOK / BMT), 256, DSMEM>>>(x, w1);
    mk_w3<<<dim3(SHH / BNT, T_TOK / BMT), 256, DSMEM>>>(x, w3);
    mk_w2<<<dim3(DIMD / BNT, T_TOK / BMT), 256, DSMEM>>>(w2, out);

    // Experts: gate -> up (silu fuse) -> down (atomic combine)
    mk_gate<<<dim3(HH / BNT, 2 * T_TOK / BMT, NE), 256, DSMEM>>>(x, gp);
    mk_up  <<<dim3(HH / BNT, 2 * T_TOK / BMT, NE), 256, DSMEM>>>(x, up);
    mk_down<<<dim3(DIMD / BNT, 2 * T_TOK / BMT, NE), 256, DSMEM>>>(dp, out);
}